// round 9
// baseline (speedup 1.0000x reference)
#include <cuda_runtime.h>

// Shapes (fixed):
//   state: [64, 128, 16]
//   block1: cols=16   -> x1 [64, 128ch, 124]   (kernel 1, materialized)
//   block2: cols=128  -> x2 [64, 1024ch, 120]  (fused; channel g used only by group g)
//   block3: cols=1024 -> x3 [64, 8192ch, 116]  (fused with dense, never stored)
//   dense:  feat = t*8192 + ch3, W [950272,2], out = tanh(x@W + bd) -> [64, 2]

#define Bz   64
#define Lin  128
#define Cin  16
#define KW   5
#define NF   8
#define L1   124
#define CH1  128
#define L2   120
#define CH2  1024
#define L3   116
#define CH3  8192
#define X2P  121          // x2sh row pitch (odd -> conflict-free b-strided LDS)

__device__ float g_x1[Bz * CH1 * L1];     // 4.06 MB
__device__ float g_partial[128 * 32];     // [b*2+a] stride 128B -> distinct L2 lines
__device__ unsigned int g_done;

// ---------------------------------------------------------------------------
// packed f32x2 helpers (Blackwell FFMA2)
// ---------------------------------------------------------------------------
typedef unsigned long long u64p;

__device__ __forceinline__ u64p f2pk(float lo, float hi) {
    u64p r; asm("mov.b64 %0, {%1,%2};" : "=l"(r) : "f"(lo), "f"(hi)); return r;
}
__device__ __forceinline__ void f2un(float& lo, float& hi, u64p v) {
    asm("mov.b64 {%0,%1}, %2;" : "=f"(lo), "=f"(hi) : "l"(v));
}
__device__ __forceinline__ u64p f2fma(u64p a, u64p b, u64p c) {
    u64p d; asm("fma.rn.f32x2 %0, %1, %2, %3;" : "=l"(d) : "l"(a), "l"(b), "l"(c)); return d;
}
__device__ __forceinline__ u64p f2relu(u64p v) {
    float lo, hi; f2un(lo, hi, v);
    return f2pk(fmaxf(lo, 0.f), fmaxf(hi, 0.f));
}

// ---------------------------------------------------------------------------
// Block 1: one CTA per (c, b). Also resets the reduction scratch.
// ---------------------------------------------------------------------------
__global__ void k_block1(const float* __restrict__ state,
                         const float* __restrict__ k1,
                         const float* __restrict__ b1) {
    const int c = blockIdx.x, b = blockIdx.y, tid = threadIdx.x;

    if (blockIdx.x == 0 && blockIdx.y == 0) {
        for (int j = tid; j < 128 * 32; j += 128) g_partial[j] = 0.f;
        if (tid == 0) g_done = 0u;
    }

    __shared__ float ssh[Lin];
    __shared__ float wsh[KW * NF];
    __shared__ float bsh[NF];

    ssh[tid] = state[(b * Lin + tid) * Cin + c];
    if (tid < KW * NF) wsh[tid] = k1[(tid >> 3) * CH1 + c * NF + (tid & 7)];
    if (tid < NF)      bsh[tid] = b1[c * NF + tid];
    __syncthreads();

    for (int i = tid; i < NF * L1; i += 128) {
        int f = i / L1, t = i - f * L1;
        float y = bsh[f];
        #pragma unroll
        for (int k = 0; k < KW; k++) y = fmaf(ssh[t + k], wsh[k * NF + f], y);
        g_x1[(b * CH1 + c * NF + f) * L1 + t] = fmaxf(y, 0.f);
    }
}

// ---------------------------------------------------------------------------
// Fused block2 + block3 + dense + last-CTA tanh epilogue.
// One CTA per group g. 256 threads = (b:64) x (ph:2 filter-pair halves) x (th:2 t-halves).
// Each thread: 2 filter-pairs x 58 t positions -> ~55 live regs, no spill.
// ---------------------------------------------------------------------------
__global__ void __launch_bounds__(256, 4) k_fused(
        const float* __restrict__ k2, const float* __restrict__ b2,
        const float* __restrict__ k3, const float* __restrict__ b3,
        const float* __restrict__ W,
        const float* __restrict__ bd, float* __restrict__ out) {
    const int g = blockIdx.x, tid = threadIdx.x;
    const int c = g >> 3;

    __shared__ float      x2sh[Bz * X2P];     // 30976 B (pitch 121)
    __shared__ ulonglong2 Wcomb[L3 * 4];      // 7424 B: [t][p] = {a0 f-pair, a1 f-pair}
    __shared__ float      x1ch[8 * L1];       // 3968 B: 8-batch staging
    __shared__ unsigned   lastf;

    // ---- W -> packed smem. float4 idx of feat0 = t*8192+g*8+2p is t*4096+g*4+p ----
    const float4* __restrict__ W4 = (const float4*)W;
    for (int i = tid; i < L3 * 4; i += 256) {
        int t = i >> 2, p = i & 3;
        float4 v = W4[t * 4096 + g * 4 + p];
        Wcomb[i] = make_ulonglong2(f2pk(v.x, v.z), f2pk(v.y, v.w));
    }

    // ---- block2 weights (broadcast) ----
    float w2r[KW];
    #pragma unroll
    for (int k = 0; k < KW; k++) w2r[k] = k2[k * CH2 + g];
    const float b2g = b2[g];

    // ---- Phase A: x2[b,g,:] for all 64 batches, 8-batch smem chunks ----
    for (int cc = 0; cc < 8; cc++) {
        for (int i = tid; i < 8 * L1; i += 256) {
            int bl = i / L1, t = i - bl * L1;
            x1ch[i] = g_x1[((cc * 8 + bl) * CH1 + c) * L1 + t];
        }
        __syncthreads();
        for (int i = tid; i < 8 * L2; i += 256) {
            int bl = i / L2, t = i - bl * L2;
            float y = b2g;
            #pragma unroll
            for (int k = 0; k < KW; k++) y = fmaf(x1ch[bl * L1 + t + k], w2r[k], y);
            x2sh[(cc * 8 + bl) * X2P + t] = fmaxf(y, 0.f);
        }
        __syncthreads();
    }

    // ---- per-thread block3 weights: 2 filter-pairs (p = 2*ph, 2*ph+1) ----
    const int b  = tid >> 2;
    const int ph = (tid >> 1) & 1;
    const int th = tid & 1;
    const int t0 = th * 58;                 // t-halves [0,58), [58,116)

    const float2* __restrict__ k3v = (const float2*)k3;
    u64p w3a[KW], w3b[KW];
    #pragma unroll
    for (int k = 0; k < KW; k++) {
        float2 va = k3v[k * (CH3 >> 1) + g * 4 + 2 * ph];
        float2 vb = k3v[k * (CH3 >> 1) + g * 4 + 2 * ph + 1];
        w3a[k] = f2pk(va.x, va.y);
        w3b[k] = f2pk(vb.x, vb.y);
    }
    u64p bpa, bpb;
    {
        const float2* __restrict__ b3v = (const float2*)b3;
        float2 va = b3v[g * 4 + 2 * ph];
        float2 vb = b3v[g * 4 + 2 * ph + 1];
        bpa = f2pk(va.x, va.y);
        bpb = f2pk(vb.x, vb.y);
    }

    // ---- Phase B ----
    const float* __restrict__ xrow = &x2sh[b * X2P];
    u64p x0 = f2pk(xrow[t0],     xrow[t0]);
    u64p x1 = f2pk(xrow[t0 + 1], xrow[t0 + 1]);
    u64p x2 = f2pk(xrow[t0 + 2], xrow[t0 + 2]);
    u64p x3 = f2pk(xrow[t0 + 3], xrow[t0 + 3]);
    u64p x4 = f2pk(xrow[t0 + 4], xrow[t0 + 4]);

    u64p acc0 = 0ull, acc1 = 0ull;
    const ulonglong2* __restrict__ wbase = &Wcomb[t0 * 4 + 2 * ph];

    #pragma unroll 2
    for (int s = 0; s < 58; s++) {
        u64p ya = bpa, yb = bpb;
        ya = f2fma(x0, w3a[0], ya);  yb = f2fma(x0, w3b[0], yb);
        ya = f2fma(x1, w3a[1], ya);  yb = f2fma(x1, w3b[1], yb);
        ya = f2fma(x2, w3a[2], ya);  yb = f2fma(x2, w3b[2], yb);
        ya = f2fma(x3, w3a[3], ya);  yb = f2fma(x3, w3b[3], yb);
        ya = f2fma(x4, w3a[4], ya);  yb = f2fma(x4, w3b[4], yb);
        ya = f2relu(ya);             yb = f2relu(yb);

        ulonglong2 wra = wbase[s * 4];        // p = 2*ph
        ulonglong2 wrb = wbase[s * 4 + 1];    // p = 2*ph+1
        acc0 = f2fma(ya, wra.x, acc0);  acc1 = f2fma(ya, wra.y, acc1);
        acc0 = f2fma(yb, wrb.x, acc0);  acc1 = f2fma(yb, wrb.y, acc1);

        // slide window; max idx t0+s+5 <= 120 which is the pad column -> in bounds
        x0 = x1; x1 = x2; x2 = x3; x3 = x4;
        float nv = xrow[t0 + s + 5];
        x4 = f2pk(nv, nv);
    }

    float lo, hi, s0, s1;
    f2un(lo, hi, acc0); s0 = lo + hi;
    f2un(lo, hi, acc1); s1 = lo + hi;

    // sum the 4 lanes (ph, th) sharing a batch
    s0 += __shfl_down_sync(0xffffffffu, s0, 2);
    s0 += __shfl_down_sync(0xffffffffu, s0, 1);
    s1 += __shfl_down_sync(0xffffffffu, s1, 2);
    s1 += __shfl_down_sync(0xffffffffu, s1, 1);
    if ((tid & 3) == 0) {
        atomicAdd(&g_partial[(b * 2 + 0) * 32], s0);
        atomicAdd(&g_partial[(b * 2 + 1) * 32], s1);
    }

    // ---- last-CTA epilogue ----
    __syncthreads();
    if (tid == 0) {
        __threadfence();
        lastf = (atomicAdd(&g_done, 1u) == (unsigned)(gridDim.x - 1));
    }
    __syncthreads();
    if (lastf && tid < 128) {
        __threadfence();
        float v = *((volatile float*)&g_partial[tid * 32]);
        out[tid] = tanhf(v + bd[tid & 1]);
    }
}

// ---------------------------------------------------------------------------
extern "C" void kernel_launch(void* const* d_in, const int* in_sizes, int n_in,
                              void* d_out, int out_size) {
    const float* state = (const float*)d_in[0];
    const float* k1    = (const float*)d_in[1];
    const float* b1    = (const float*)d_in[2];
    const float* k2    = (const float*)d_in[3];
    const float* b2    = (const float*)d_in[4];
    const float* k3    = (const float*)d_in[5];
    const float* b3    = (const float*)d_in[6];
    const float* W     = (const float*)d_in[7];
    const float* bd    = (const float*)d_in[8];
    float* out = (float*)d_out;

    k_block1<<<dim3(16, 64), 128>>>(state, k1, b1);
    k_fused<<<1024, 256>>>(k2, b2, k3, b3, W, bd, out);
}

// round 11
// speedup vs baseline: 1.3765x; 1.3765x over previous
#include <cuda_runtime.h>

// Shapes (fixed):
//   state: [64, 128, 16]
//   block1: cols=16   -> x1 [64, 128ch, 124]   (kernel 1, materialized)
//   block2: cols=128  -> x2 [64, 1024ch, 120]  (fused; channel g used only by group g)
//   block3: cols=1024 -> x3 [64, 8192ch, 116]  (fused with dense, never stored)
//   dense:  feat = t*8192 + ch3, W [950272,2], out = tanh(x@W + bd) -> [64, 2]

#define Bz   64
#define Lin  128
#define Cin  16
#define KW   5
#define NF   8
#define L1   124
#define CH1  128
#define L2   120
#define CH2  1024
#define L3   116
#define CH3  8192
#define TH   58            // t-half length (L3/2)
#define XPP  63            // xp pitch in pairs (odd -> conflict-free b-strided LDS.64)

__device__ float g_x1[Bz * CH1 * L1];     // 4.06 MB
__device__ float g_partial[128 * 32];     // [b*2+a] stride 128B -> distinct L2 lines
__device__ unsigned int g_done;

// ---------------------------------------------------------------------------
// packed f32x2 helpers. Pack/unpack via unions (register-pair naming, no MOVs);
// only the FMA itself is asm.
// ---------------------------------------------------------------------------
typedef unsigned long long u64p;
union pk2 { u64p u; float2 f; uint2 h; };

__device__ __forceinline__ u64p f2pk(float lo, float hi) {
    pk2 x; x.f.x = lo; x.f.y = hi; return x.u;
}
__device__ __forceinline__ u64p f2fma(u64p a, u64p b, u64p c) {
    u64p d; asm("fma.rn.f32x2 %0, %1, %2, %3;" : "=l"(d) : "l"(a), "l"(b), "l"(c)); return d;
}
// relu per 32-bit half: negative (sign bit set) -> 0.  SHF + LOP3(and-not), no movs.
__device__ __forceinline__ u64p f2relu(u64p v) {
    pk2 x; x.u = v;
    x.h.x &= ~(unsigned)((int)x.h.x >> 31);
    x.h.y &= ~(unsigned)((int)x.h.y >> 31);
    return x.u;
}

// ---------------------------------------------------------------------------
// Block 1: one CTA per (c, b). Also resets the reduction scratch.
// ---------------------------------------------------------------------------
__global__ void k_block1(const float* __restrict__ state,
                         const float* __restrict__ k1,
                         const float* __restrict__ b1) {
    const int c = blockIdx.x, b = blockIdx.y, tid = threadIdx.x;

    if (blockIdx.x == 0 && blockIdx.y == 0) {
        for (int j = tid; j < 128 * 32; j += 128) g_partial[j] = 0.f;
        if (tid == 0) g_done = 0u;
    }

    __shared__ float ssh[Lin];
    __shared__ float wsh[KW * NF];
    __shared__ float bsh[NF];

    ssh[tid] = state[(b * Lin + tid) * Cin + c];
    if (tid < KW * NF) wsh[tid] = k1[(tid >> 3) * CH1 + c * NF + (tid & 7)];
    if (tid < NF)      bsh[tid] = b1[c * NF + tid];
    __syncthreads();

    for (int i = tid; i < NF * L1; i += 128) {
        int f = i / L1, t = i - f * L1;
        float y = bsh[f];
        #pragma unroll
        for (int k = 0; k < KW; k++) y = fmaf(ssh[t + k], wsh[k * NF + f], y);
        g_x1[(b * CH1 + c * NF + f) * L1 + t] = fmaxf(y, 0.f);
    }
}

// ---------------------------------------------------------------------------
// Fused block2 + block3 + dense + last-CTA tanh epilogue.
// One CTA per group g; 256 threads = (b:64) x (fp:4 filter pairs).
// Packing axis = t-halves: every packed register holds values at (t, t+58).
//   xp[b][p] = (x2[b,p], x2[b,p+58])   p in [0,62)  -- pre-packed in phase A
//   conv weights broadcast-packed (w,w), hoisted
//   Wp[s][fp] = 4 pairs {(W[s,f,a], W[s+58,f,a])} for f in {2fp,2fp+1}, a in {0,1}
// ---------------------------------------------------------------------------
__global__ void __launch_bounds__(256, 4) k_fused(
        const float* __restrict__ k2, const float* __restrict__ b2,
        const float* __restrict__ k3, const float* __restrict__ b3,
        const float* __restrict__ W,
        const float* __restrict__ bd, float* __restrict__ out) {
    const int g = blockIdx.x, tid = threadIdx.x;
    const int c = g >> 3;

    __shared__ u64p       xp[Bz * XPP];        // 32256 B
    __shared__ ulonglong2 Wp[TH * 4 * 2];      // 7424 B: [ (s*4+fp)*2 + {0,1} ]
    __shared__ float      x1ch[16 * L1];       // 7936 B staging
    __shared__ unsigned   lastf;

    // ---- W -> t-half-packed smem (each float4 = {W[f0,a0],W[f0,a1],W[f1,a0],W[f1,a1]}) ----
    const float4* __restrict__ W4 = (const float4*)W;
    for (int i = tid; i < TH * 4; i += 256) {
        int s = i >> 2, fp = i & 3;
        float4 va = W4[s * 4096 + g * 4 + fp];          // t = s
        float4 vb = W4[(s + TH) * 4096 + g * 4 + fp];   // t = s + 58
        Wp[2 * i]     = make_ulonglong2(f2pk(va.x, vb.x), f2pk(va.y, vb.y)); // f0: a0, a1
        Wp[2 * i + 1] = make_ulonglong2(f2pk(va.z, vb.z), f2pk(va.w, vb.w)); // f1: a0, a1
    }

    // ---- block2 weights (broadcast) ----
    float w2r[KW];
    #pragma unroll
    for (int k = 0; k < KW; k++) w2r[k] = k2[k * CH2 + g];
    const float b2g = b2[g];

    // ---- Phase A: x2[b,g,:] packed into xp, 4 chunks of 16 batches ----
    for (int cc = 0; cc < 4; cc++) {
        for (int i = tid; i < 16 * L1; i += 256) {
            int bl = i / L1, t = i - bl * L1;
            x1ch[i] = g_x1[((cc * 16 + bl) * CH1 + c) * L1 + t];
        }
        __syncthreads();
        for (int i = tid; i < 16 * L2; i += 256) {
            int bl = i / L2, t = i - bl * L2;
            float y = b2g;
            #pragma unroll
            for (int k = 0; k < KW; k++) y = fmaf(x1ch[bl * L1 + t + k], w2r[k], y);
            y = fmaxf(y, 0.f);
            float* row = (float*)&xp[(cc * 16 + bl) * XPP];
            if (t < TH + 4)  row[t * 2] = y;                 // lo half: p = t      (t < 62)
            if (t >= TH)     row[(t - TH) * 2 + 1] = y;      // hi half: p = t - 58
        }
        __syncthreads();
    }

    // ---- hoisted block3 weights/bias, broadcast-packed per filter ----
    const int b  = tid >> 2;
    const int fp = tid & 3;
    const int f0 = g * NF + 2 * fp;

    u64p wA[KW], wB[KW];
    #pragma unroll
    for (int k = 0; k < KW; k++) {
        float a = k3[k * CH3 + f0], bq = k3[k * CH3 + f0 + 1];
        wA[k] = f2pk(a, a);
        wB[k] = f2pk(bq, bq);
    }
    const float ba_s = b3[f0], bb_s = b3[f0 + 1];
    const u64p bA = f2pk(ba_s, ba_s), bB = f2pk(bb_s, bb_s);

    // ---- Phase B ----
    const u64p* __restrict__ xrow = &xp[b * XPP];
    const ulonglong2* __restrict__ wbase = &Wp[fp * 2];

    u64p x0 = xrow[0], x1 = xrow[1], x2 = xrow[2], x3 = xrow[3], x4 = xrow[4];
    u64p acc0 = 0ull, acc1 = 0ull;

    #pragma unroll 2
    for (int s = 0; s < TH; s++) {
        u64p ya = bA, yb = bB;
        ya = f2fma(x0, wA[0], ya);  yb = f2fma(x0, wB[0], yb);
        ya = f2fma(x1, wA[1], ya);  yb = f2fma(x1, wB[1], yb);
        ya = f2fma(x2, wA[2], ya);  yb = f2fma(x2, wB[2], yb);
        ya = f2fma(x3, wA[3], ya);  yb = f2fma(x3, wB[3], yb);
        ya = f2fma(x4, wA[4], ya);  yb = f2fma(x4, wB[4], yb);
        ya = f2relu(ya);            yb = f2relu(yb);

        ulonglong2 w0 = wbase[s * 8];        // f0: (a0, a1) pairs
        ulonglong2 w1 = wbase[s * 8 + 1];    // f1: (a0, a1) pairs
        acc0 = f2fma(ya, w0.x, acc0);  acc1 = f2fma(ya, w0.y, acc1);
        acc0 = f2fma(yb, w1.x, acc0);  acc1 = f2fma(yb, w1.y, acc1);

        // slide; s=57 reads xrow[62] = in-bounds pad slot (value unused)
        x0 = x1; x1 = x2; x2 = x3; x3 = x4;
        x4 = xrow[s + 5];
    }

    pk2 r0, r1; r0.u = acc0; r1.u = acc1;
    float s0 = r0.f.x + r0.f.y;          // halves = disjoint t ranges
    float s1 = r1.f.x + r1.f.y;

    // sum the 4 fp lanes sharing a batch
    s0 += __shfl_down_sync(0xffffffffu, s0, 2);
    s0 += __shfl_down_sync(0xffffffffu, s0, 1);
    s1 += __shfl_down_sync(0xffffffffu, s1, 2);
    s1 += __shfl_down_sync(0xffffffffu, s1, 1);
    if (fp == 0) {
        atomicAdd(&g_partial[(b * 2 + 0) * 32], s0);
        atomicAdd(&g_partial[(b * 2 + 1) * 32], s1);
    }

    // ---- last-CTA epilogue ----
    __syncthreads();
    if (tid == 0) {
        __threadfence();
        lastf = (atomicAdd(&g_done, 1u) == (unsigned)(gridDim.x - 1));
    }
    __syncthreads();
    if (lastf && tid < 128) {
        __threadfence();
        float v = *((volatile float*)&g_partial[tid * 32]);
        out[tid] = tanhf(v + bd[tid & 1]);
    }
}

// ---------------------------------------------------------------------------
extern "C" void kernel_launch(void* const* d_in, const int* in_sizes, int n_in,
                              void* d_out, int out_size) {
    const float* state = (const float*)d_in[0];
    const float* k1    = (const float*)d_in[1];
    const float* b1    = (const float*)d_in[2];
    const float* k2    = (const float*)d_in[3];
    const float* b2    = (const float*)d_in[4];
    const float* k3    = (const float*)d_in[5];
    const float* b3    = (const float*)d_in[6];
    const float* W     = (const float*)d_in[7];
    const float* bd    = (const float*)d_in[8];
    float* out = (float*)d_out;

    k_block1<<<dim3(16, 64), 128>>>(state, k1, b1);
    k_fused<<<1024, 256>>>(k2, b2, k3, b3, W, bd, out);
}